// round 12
// baseline (speedup 1.0000x reference)
#include <cuda_runtime.h>
#include <cuda_bf16.h>
#include <math_constants.h>
#include <cstdint>

#define HIDDEN 768
#define NH     12
#define DH     64
#define BATCH  4
#define SEQ    2048
#define MTOT   (BATCH*SEQ)   // 8192

// ---------------------------------------------------------------------------
// Scratch (__device__ globals)
// ---------------------------------------------------------------------------
__device__ __nv_bfloat16 g_xhi[(size_t)MTOT * HIDDEN];
__device__ __nv_bfloat16 g_xlo[(size_t)MTOT * HIDDEN];
__device__ __nv_bfloat16 g_whi[4][(size_t)HIDDEN * HIDDEN];
__device__ __nv_bfloat16 g_wlo[4][(size_t)HIDDEN * HIDDEN];
__device__ __nv_bfloat16 g_qhi[(size_t)MTOT * HIDDEN];
__device__ __nv_bfloat16 g_qlo[(size_t)MTOT * HIDDEN];
__device__ __nv_bfloat16 g_khi[(size_t)MTOT * HIDDEN];
__device__ __nv_bfloat16 g_klo[(size_t)MTOT * HIDDEN];
__device__ __nv_bfloat16 g_vhi[(size_t)MTOT * HIDDEN];
__device__ __nv_bfloat16 g_vlo[(size_t)MTOT * HIDDEN];
__device__ __nv_bfloat16 g_chi[(size_t)MTOT * HIDDEN];
__device__ __nv_bfloat16 g_clo[(size_t)MTOT * HIDDEN];

// ---------------------------------------------------------------------------
// PTX primitives (baseline PTX only — valid on compute_103 target)
// ---------------------------------------------------------------------------
__device__ __forceinline__ uint32_t smem_u32(const void* p) {
    uint32_t a;
    asm("{ .reg .u64 t; cvta.to.shared.u64 t, %1; cvt.u32.u64 %0, t; }"
        : "=r"(a) : "l"(p));
    return a;
}

__device__ __forceinline__ void mma_bf16(float* d, const uint32_t* a, const uint32_t* b) {
    asm volatile(
        "mma.sync.aligned.m16n8k16.row.col.f32.bf16.bf16.f32 "
        "{%0,%1,%2,%3}, {%4,%5,%6,%7}, {%8,%9}, {%0,%1,%2,%3};"
        : "+f"(d[0]), "+f"(d[1]), "+f"(d[2]), "+f"(d[3])
        : "r"(a[0]), "r"(a[1]), "r"(a[2]), "r"(a[3]), "r"(b[0]), "r"(b[1]));
}

__device__ __forceinline__ void ldsm_x4(uint32_t* r, uint32_t addr) {
    asm volatile("ldmatrix.sync.aligned.m8n8.x4.shared.b16 {%0,%1,%2,%3}, [%4];"
                 : "=r"(r[0]), "=r"(r[1]), "=r"(r[2]), "=r"(r[3]) : "r"(addr));
}
__device__ __forceinline__ void ldsm_x4_t(uint32_t* r, uint32_t addr) {
    asm volatile("ldmatrix.sync.aligned.m8n8.x4.trans.shared.b16 {%0,%1,%2,%3}, [%4];"
                 : "=r"(r[0]), "=r"(r[1]), "=r"(r[2]), "=r"(r[3]) : "r"(addr));
}

__device__ __forceinline__ void cp_async16(uint32_t dst, const void* src) {
    asm volatile(
        "{ .reg .u64 g; cvta.to.global.u64 g, %1; "
        "cp.async.cg.shared.global [%0], [g], 16; }"
        :: "r"(dst), "l"(src));
}
#define CP_COMMIT() asm volatile("cp.async.commit_group;" ::: "memory")
#define CP_WAIT(n)  asm volatile("cp.async.wait_group %0;" :: "n"(n) : "memory")

__device__ __forceinline__ uint32_t bfpack(__nv_bfloat16 a, __nv_bfloat16 b) {
    __nv_bfloat162 t; t.x = a; t.y = b;
    return *(uint32_t*)&t;
}
__device__ __forceinline__ void split2(float a, float b, uint32_t& hi, uint32_t& lo) {
    __nv_bfloat16 ha = __float2bfloat16(a), hb = __float2bfloat16(b);
    __nv_bfloat16 la = __float2bfloat16(a - __bfloat162float(ha));
    __nv_bfloat16 lb = __float2bfloat16(b - __bfloat162float(hb));
    hi = bfpack(ha, hb);
    lo = bfpack(la, lb);
}

// ---------------------------------------------------------------------------
// fp32 -> bf16 hi/lo split kernels
// ---------------------------------------------------------------------------
__device__ __forceinline__ void split_body(const float* __restrict__ src,
                                           __nv_bfloat16* __restrict__ hi,
                                           __nv_bfloat16* __restrict__ lo, int i)
{
    float4 v = ((const float4*)src)[i];
    uint32_t h0, l0, h1, l1;
    split2(v.x, v.y, h0, l0);
    split2(v.z, v.w, h1, l1);
    ((uint32_t*)hi)[2 * i + 0] = h0;
    ((uint32_t*)hi)[2 * i + 1] = h1;
    ((uint32_t*)lo)[2 * i + 0] = l0;
    ((uint32_t*)lo)[2 * i + 1] = l1;
}

__global__ __launch_bounds__(256) void split_x_kernel(const float* __restrict__ src)
{
    int i = blockIdx.x * blockDim.x + threadIdx.x;
    if (i < MTOT * HIDDEN / 4) split_body(src, g_xhi, g_xlo, i);
}

__global__ __launch_bounds__(256) void split_w_kernel(const float* __restrict__ w0,
                                                      const float* __restrict__ w1,
                                                      const float* __restrict__ w2,
                                                      const float* __restrict__ w3)
{
    int z = blockIdx.y;
    const float* src = (z == 0) ? w0 : (z == 1) ? w1 : (z == 2) ? w2 : w3;
    int i = blockIdx.x * blockDim.x + threadIdx.x;
    if (i < HIDDEN * HIDDEN / 4) split_body(src, g_whi[z], g_wlo[z], i);
}

// ---------------------------------------------------------------------------
// HMMA bf16-split GEMM core, 128(M) x 256(N) CTA tile, BK=32, 2-stage cp.async.
// 256 threads, 8 warps in 2x4: warp tile 64x64. LDSM:MMA = 1:12 per chunk.
// Buffer 48KB: Ah 0, Al 8192, Bh 16384, Bl 32768. 2 buffers = 96KB.
// Swizzle: chunk c ^ ((row>>1)&3).
// ---------------------------------------------------------------------------
#define KCH (HIDDEN / 32)    // 24
#define GEMM_BUF 49152
#define GEMM_SMEM (2 * GEMM_BUF)

extern __shared__ uint4 dynsm[];

struct GemmFrag {
    float acc[4][8][4];
    int lane, wm, wn;
};

__device__ __forceinline__ void hmma_core(const __nv_bfloat16* __restrict__ Ahi,
                                          const __nv_bfloat16* __restrict__ Alo,
                                          const __nv_bfloat16* __restrict__ Bhi,
                                          const __nv_bfloat16* __restrict__ Blo,
                                          int bm, int bn, GemmFrag& fr)
{
    const uint32_t sb = smem_u32(dynsm);

    const int tid  = threadIdx.x;
    const int lane = tid & 31;
    const int wid  = tid >> 5;
    fr.lane = lane;
    fr.wm   = (wid & 1) * 64;
    fr.wn   = (wid >> 1) * 64;

    // staging: A 128 rows x 4 chunks (2 per thread), B 256 rows x 4 chunks (4/thread)
    const int rA = tid >> 1;
    const int cA = (tid & 1) * 2;
    uint32_t dstA[2], dstB[4];
#pragma unroll
    for (int k = 0; k < 2; k++)
        dstA[k] = (uint32_t)(rA * 4 + ((cA + k) ^ ((rA >> 1) & 3))) * 16;
#pragma unroll
    for (int c = 0; c < 4; c++)
        dstB[c] = (uint32_t)(tid * 4 + (c ^ ((tid >> 1) & 3))) * 16;

    const uint4* Ah4 = (const uint4*)Ahi;
    const uint4* Al4 = (const uint4*)Alo;
    const uint4* Bh4 = (const uint4*)Bhi;
    const uint4* Bl4 = (const uint4*)Blo;
    const int rowstride4 = HIDDEN / 8;   // 96
    const size_t srcA = (size_t)(bm + rA) * rowstride4 + cA;
    const size_t srcB = (size_t)(bn + tid) * rowstride4;

    // ldmatrix offsets
    uint32_t offA[2][4], offB[2][4];
#pragma unroll
    for (int mi = 0; mi < 4; mi++) {
        int rowA = fr.wm + mi * 16 + (lane & 15);
        int keyA = (rowA >> 1) & 3;
#pragma unroll
        for (int ks = 0; ks < 2; ks++) {
            int c = ks * 2 + (lane >> 4);
            offA[ks][mi] = rowA * 64 + ((c ^ keyA) << 4);
        }
    }
#pragma unroll
    for (int p = 0; p < 4; p++) {       // ni pair: (2p, 2p+1)
        int rowB = fr.wn + (2 * p + ((lane >> 4) & 1)) * 8 + (lane & 7);
        int keyB = (rowB >> 1) & 3;
#pragma unroll
        for (int ks = 0; ks < 2; ks++) {
            int c = ks * 2 + ((lane >> 3) & 1);
            offB[ks][p] = rowB * 64 + ((c ^ keyB) << 4);
        }
    }

#pragma unroll
    for (int mi = 0; mi < 4; mi++)
#pragma unroll
        for (int ni = 0; ni < 8; ni++)
#pragma unroll
            for (int t = 0; t < 4; t++) fr.acc[mi][ni][t] = 0.0f;

    auto stage = [&](int kc, int buf) {
        const size_t ko = (size_t)kc * 4;
        uint32_t d = sb + (uint32_t)buf * GEMM_BUF;
#pragma unroll
        for (int k = 0; k < 2; k++) {
            cp_async16(d + dstA[k],        Ah4 + srcA + ko + k);
            cp_async16(d + 8192 + dstA[k], Al4 + srcA + ko + k);
        }
#pragma unroll
        for (int c = 0; c < 4; c++) {
            cp_async16(d + 16384 + dstB[c], Bh4 + srcB + ko + c);
            cp_async16(d + 32768 + dstB[c], Bl4 + srcB + ko + c);
        }
    };

    stage(0, 0);
    CP_COMMIT();

    for (int kc = 0; kc < KCH; kc++) {
        if (kc + 1 < KCH) {
            stage(kc + 1, (kc + 1) & 1);
            CP_COMMIT();
            CP_WAIT(1);
        } else {
            CP_WAIT(0);
        }
        __syncthreads();

        const uint32_t bAh = sb + (uint32_t)(kc & 1) * GEMM_BUF;
        const uint32_t bAl = bAh + 8192;
        const uint32_t bBh = bAh + 16384;
        const uint32_t bBl = bAh + 32768;

#pragma unroll
        for (int ks = 0; ks < 2; ks++) {
            uint32_t ah[4][4], al[4][4];
#pragma unroll
            for (int mi = 0; mi < 4; mi++) {
                ldsm_x4(ah[mi], bAh + offA[ks][mi]);
                ldsm_x4(al[mi], bAl + offA[ks][mi]);
            }
            // process n-pairs: per pair load bh/bl then 24 MMAs (term-grouped)
#pragma unroll
            for (int p = 0; p < 4; p++) {
                uint32_t bh[4], bl[4];
                ldsm_x4(bh, bBh + offB[ks][p]);
                ldsm_x4(bl, bBl + offB[ks][p]);
#pragma unroll
                for (int mi = 0; mi < 4; mi++) {
                    mma_bf16(fr.acc[mi][2 * p + 0], ah[mi], &bh[0]);
                    mma_bf16(fr.acc[mi][2 * p + 1], ah[mi], &bh[2]);
                }
#pragma unroll
                for (int mi = 0; mi < 4; mi++) {
                    mma_bf16(fr.acc[mi][2 * p + 0], ah[mi], &bl[0]);
                    mma_bf16(fr.acc[mi][2 * p + 1], ah[mi], &bl[2]);
                }
#pragma unroll
                for (int mi = 0; mi < 4; mi++) {
                    mma_bf16(fr.acc[mi][2 * p + 0], al[mi], &bh[0]);
                    mma_bf16(fr.acc[mi][2 * p + 1], al[mi], &bh[2]);
                }
            }
        }
        __syncthreads();
    }
}

// qkv: epilogue writes bf16 hi/lo (Q pre-scaled by 1/8)
__global__ __launch_bounds__(256) void qkv_mma_kernel()
{
    const int z = blockIdx.z;
    __nv_bfloat16 *Ohi, *Olo;
    float scale;
    if (z == 0)      { Ohi = g_qhi; Olo = g_qlo; scale = 0.125f; }
    else if (z == 1) { Ohi = g_khi; Olo = g_klo; scale = 1.0f; }
    else             { Ohi = g_vhi; Olo = g_vlo; scale = 1.0f; }

    GemmFrag fr;
    hmma_core(g_xhi, g_xlo, g_whi[z], g_wlo[z], blockIdx.y * 128, blockIdx.x * 256, fr);

    const int bm = blockIdx.y * 128, bn = blockIdx.x * 256;
#pragma unroll
    for (int mi = 0; mi < 4; mi++) {
        int row = bm + fr.wm + mi * 16 + (fr.lane >> 2);
#pragma unroll
        for (int ni = 0; ni < 8; ni++) {
            int col = bn + fr.wn + ni * 8 + ((fr.lane & 3) << 1);
            uint32_t h0, l0, h1, l1;
            split2(fr.acc[mi][ni][0] * scale, fr.acc[mi][ni][1] * scale, h0, l0);
            split2(fr.acc[mi][ni][2] * scale, fr.acc[mi][ni][3] * scale, h1, l1);
            *(uint32_t*)(Ohi + (size_t)row * HIDDEN + col) = h0;
            *(uint32_t*)(Olo + (size_t)row * HIDDEN + col) = l0;
            *(uint32_t*)(Ohi + (size_t)(row + 8) * HIDDEN + col) = h1;
            *(uint32_t*)(Olo + (size_t)(row + 8) * HIDDEN + col) = l1;
        }
    }
}

// proj: fp32 out
__global__ __launch_bounds__(256) void proj_mma_kernel(float* __restrict__ out)
{
    GemmFrag fr;
    hmma_core(g_chi, g_clo, g_whi[3], g_wlo[3], blockIdx.y * 128, blockIdx.x * 256, fr);

    const int bm = blockIdx.y * 128, bn = blockIdx.x * 256;
#pragma unroll
    for (int mi = 0; mi < 4; mi++) {
        int row = bm + fr.wm + mi * 16 + (fr.lane >> 2);
#pragma unroll
        for (int ni = 0; ni < 8; ni++) {
            int col = bn + fr.wn + ni * 8 + ((fr.lane & 3) << 1);
            *(float2*)(out + (size_t)row * HIDDEN + col) =
                make_float2(fr.acc[mi][ni][0], fr.acc[mi][ni][1]);
            *(float2*)(out + (size_t)(row + 8) * HIDDEN + col) =
                make_float2(fr.acc[mi][ni][2], fr.acc[mi][ni][3]);
        }
    }
}

// ---------------------------------------------------------------------------
// Tensor-core flash attention (round-10 version, 379us measured).
// 128 threads/CTA (4 warps x 16 q-rows = 64 q). cp.async double-buffered.
// Buffer (32KB): Khi 0, Klo 8192, Vhi 16384, Vlo 24576. Swizzle c ^ (row&7).
// ---------------------------------------------------------------------------
#define ATTN_SMEM 65536

__global__ __launch_bounds__(128, 3) void attn_mma_kernel()
{
    const uint32_t sb = smem_u32(dynsm);

    const int tid  = threadIdx.x;
    const int lane = tid & 31;
    const int wid  = tid >> 5;          // 0..3
    const int bh   = blockIdx.y;
    const int b    = bh / NH;
    const int h    = bh % NH;
    const int q0   = blockIdx.x * 64;

    const size_t base = (size_t)b * SEQ * HIDDEN + h * DH;

    // ---- stage Q (64 rows; hi at 0, lo at 8192) ----
#pragma unroll
    for (int j = 0; j < 4; j++) {
        int idx = j * 128 + tid;
        int r = idx >> 3, c = idx & 7;
        uint32_t d = (uint32_t)(r * 8 + (c ^ (r & 7))) * 16;
        cp_async16(sb + d,        (const uint4*)(g_qhi + base + (size_t)(q0 + r) * HIDDEN) + c);
        cp_async16(sb + 8192 + d, (const uint4*)(g_qlo + base + (size_t)(q0 + r) * HIDDEN) + c);
    }
    CP_COMMIT();
    CP_WAIT(0);
    __syncthreads();

    // ---- Q fragments (held in registers for whole kernel) ----
    uint32_t qh[4][4], ql[4][4];
    {
        int qrow = wid * 16 + (lane & 15);
        int key  = qrow & 7;
#pragma unroll
        for (int ks = 0; ks < 4; ks++) {
            int c = ks * 2 + (lane >> 4);
            uint32_t off = (uint32_t)(qrow * 8 + (c ^ key)) * 16;
            ldsm_x4(qh[ks], sb + off);
            ldsm_x4(ql[ks], sb + 8192 + off);
        }
    }
    __syncthreads();

    float accO[8][4];
#pragma unroll
    for (int n = 0; n < 8; n++)
#pragma unroll
        for (int t = 0; t < 4; t++) accO[n][t] = 0.0f;
    float m0 = -CUDART_INF_F, m1 = -CUDART_INF_F, l0 = 0.0f, l1 = 0.0f;

    const int sr = tid >> 3;           // 0..15
    const int sc = tid & 7;
    uint32_t sd[4];
#pragma unroll
    for (int u = 0; u < 4; u++) {
        int row = sr + u * 16;
        sd[u] = (uint32_t)(row * 8 + (sc ^ (row & 7))) * 16;
    }

    auto stageKV = [&](int kt, int buf) {
        uint32_t d = sb + (uint32_t)buf * 32768;
#pragma unroll
        for (int u = 0; u < 4; u++) {
            size_t roff = base + (size_t)(kt + sr + u * 16) * HIDDEN;
            cp_async16(d + sd[u],         (const uint4*)(g_khi + roff) + sc);
            cp_async16(d + 8192 + sd[u],  (const uint4*)(g_klo + roff) + sc);
            cp_async16(d + 16384 + sd[u], (const uint4*)(g_vhi + roff) + sc);
            cp_async16(d + 24576 + sd[u], (const uint4*)(g_vlo + roff) + sc);
        }
    };

    stageKV(0, 0);
    CP_COMMIT();

    for (int it = 0; it < SEQ / 64; it++) {
        if (it + 1 < SEQ / 64) {
            stageKV((it + 1) * 64, (it + 1) & 1);
            CP_COMMIT();
            CP_WAIT(1);
        } else {
            CP_WAIT(0);
        }
        __syncthreads();

        const uint32_t bKh = sb + (uint32_t)(it & 1) * 32768;
        const uint32_t bKl = bKh + 8192;
        const uint32_t bVh = bKh + 16384;
        const uint32_t bVl = bKh + 24576;

        // ---- S = Q.K^T (3-term), fragments preloaded per pair-of-pairs ----
        float s[8][4];
#pragma unroll
        for (int n = 0; n < 8; n++)
#pragma unroll
            for (int t = 0; t < 4; t++) s[n][t] = 0.0f;

#pragma unroll
        for (int ks = 0; ks < 4; ks++) {
#pragma unroll
            for (int pp = 0; pp < 4; pp += 2) {
                uint32_t kh4[2][4], kl4[2][4];
#pragma unroll
                for (int d2 = 0; d2 < 2; d2++) {
                    int p = pp + d2;
                    int krow = (2 * p + ((lane >> 4) & 1)) * 8 + (lane & 7);
                    int c = ks * 2 + ((lane >> 3) & 1);
                    uint32_t off = (uint32_t)(krow * 8 + (c ^ (lane & 7))) * 16;
                    ldsm_x4(kh4[d2], bKh + off);
                    ldsm_x4(kl4[d2], bKl + off);
                }
                mma_bf16(s[2 * pp + 0], qh[ks], &kh4[0][0]);
                mma_bf16(s[2 * pp + 1], qh[ks], &kh4[0][2]);
                mma_bf16(s[2 * pp + 2], qh[ks], &kh4[1][0]);
                mma_bf16(s[2 * pp + 3], qh[ks], &kh4[1][2]);
                mma_bf16(s[2 * pp + 0], qh[ks], &kl4[0][0]);
                mma_bf16(s[2 * pp + 1], qh[ks], &kl4[0][2]);
                mma_bf16(s[2 * pp + 2], qh[ks], &kl4[1][0]);
                mma_bf16(s[2 * pp + 3], qh[ks], &kl4[1][2]);
                mma_bf16(s[2 * pp + 0], ql[ks], &kh4[0][0]);
                mma_bf16(s[2 * pp + 1], ql[ks], &kh4[0][2]);
                mma_bf16(s[2 * pp + 2], ql[ks], &kh4[1][0]);
                mma_bf16(s[2 * pp + 3], ql[ks], &kh4[1][2]);
            }
        }

        // ---- online softmax (rows r = lane>>2 and r+8) ----
        float rmax0 = -CUDART_INF_F, rmax1 = -CUDART_INF_F;
#pragma unroll
        for (int n = 0; n < 8; n++) {
            rmax0 = fmaxf(rmax0, fmaxf(s[n][0], s[n][1]));
            rmax1 = fmaxf(rmax1, fmaxf(s[n][2], s[n][3]));
        }
        rmax0 = fmaxf(rmax0, __shfl_xor_sync(0xffffffffu, rmax0, 1));
        rmax0 = fmaxf(rmax0, __shfl_xor_sync(0xffffffffu, rmax0, 2));
        rmax1 = fmaxf(rmax1, __shfl_xor_sync(0xffffffffu, rmax1, 1));
        rmax1 = fmaxf(rmax1, __shfl_xor_sync(0xffffffffu, rmax1, 2));
        float mn0 = fmaxf(m0, rmax0), mn1 = fmaxf(m1, rmax1);
        float a0 = __expf(m0 - mn0), a1 = __expf(m1 - mn1);
        float sum0 = 0.0f, sum1 = 0.0f;
#pragma unroll
        for (int n = 0; n < 8; n++) {
            s[n][0] = __expf(s[n][0] - mn0);
            s[n][1] = __expf(s[n][1] - mn0);
            s[n][2] = __expf(s[n][2] - mn1);
            s[n][3] = __expf(s[n][3] - mn1);
            sum0 += s[n][0] + s[n][1];
            sum1 += s[n][2] + s[n][3];
        }
        sum0 += __shfl_xor_sync(0xffffffffu, sum0, 1);
        sum0 += __shfl_xor_sync(0xffffffffu, sum0, 2);
        sum1 += __shfl_xor_sync(0xffffffffu, sum1, 1);
        sum1 += __shfl_xor_sync(0xffffffffu, sum1, 2);
        l0 = l0 * a0 + sum0;
        l1 = l1 * a1 + sum1;
        m0 = mn0; m1 = mn1;
#pragma unroll
        for (int n = 0; n < 8; n++) {
            accO[n][0] *= a0; accO[n][1] *= a0;
            accO[n][2] *= a1; accO[n][3] *= a1;
        }

        // ---- O += P.V (3-term); P converted per-j; V via ldmatrix.x4.trans ----
#pragma unroll
        for (int j = 0; j < 4; j++) {
            uint32_t ph[4], pl[4];
            split2(s[2 * j][0],     s[2 * j][1],     ph[0], pl[0]);
            split2(s[2 * j][2],     s[2 * j][3],     ph[1], pl[1]);
            split2(s[2 * j + 1][0], s[2 * j + 1][1], ph[2], pl[2]);
            split2(s[2 * j + 1][2], s[2 * j + 1][3], ph[3], pl[3]);
            int vrow = j * 16 + (lane & 15);
#pragma unroll
            for (int qq = 0; qq < 4; qq += 2) {
                uint32_t vh4[2][4], vl4[2][4];
#pragma unroll
                for (int d2 = 0; d2 < 2; d2++) {
                    int c = 2 * (qq + d2) + ((lane >> 4) & 1);
                    uint32_t off = (uint32_t)(vrow * 8 + (c ^ (vrow & 7))) * 16;
                    ldsm_x4_t(vh4[d2], bVh + off);
                    ldsm_x4_t(vl4[d2], bVl + off);
                }
                mma_bf16(accO[2 * qq + 0], ph, &vh4[0][0]);
                mma_bf16(accO[2 * qq + 1], ph, &vh4[0][2]);
                mma_bf16(accO[2 * qq + 2], ph, &vh4[1][0]);
                mma_bf16(accO[2 * qq + 3], ph, &vh4[1][2]);
                mma_bf16(accO[2 * qq + 0], ph, &vl4[0][0]);
                mma_bf16(accO[2 * qq + 1], ph, &vl4[0][2]);
                mma_bf16(accO[2 * qq + 2], ph, &vl4[1][0]);
                mma_bf16(accO[2 * qq + 3], ph, &vl4[1][2]);
                mma_bf16(accO[2 * qq + 0], pl, &vh4[0][0]);
                mma_bf16(accO[2 * qq + 1], pl, &vh4[0][2]);
                mma_bf16(accO[2 * qq + 2], pl, &vh4[1][0]);
                mma_bf16(accO[2 * qq + 3], pl, &vh4[1][2]);
            }
        }
        __syncthreads();
    }

    // ---- epilogue: normalize, write ctx hi/lo bf16 ----
    float inv0 = 1.0f / l0, inv1 = 1.0f / l1;
    int row = q0 + wid * 16 + (lane >> 2);
#pragma unroll
    for (int n2 = 0; n2 < 8; n2++) {
        int col = n2 * 8 + ((lane & 3) << 1);
        uint32_t h0, lo0, h1, lo1;
        split2(accO[n2][0] * inv0, accO[n2][1] * inv0, h0, lo0);
        split2(accO[n2][2] * inv1, accO[n2][3] * inv1, h1, lo1);
        size_t p0 = base + (size_t)row * HIDDEN + col;
        size_t p1 = base + (size_t)(row + 8) * HIDDEN + col;
        *(uint32_t*)(g_chi + p0) = h0;
        *(uint32_t*)(g_clo + p0) = lo0;
        *(uint32_t*)(g_chi + p1) = h1;
        *(uint32_t*)(g_clo + p1) = lo1;
    }
}

// ---------------------------------------------------------------------------
extern "C" void kernel_launch(void* const* d_in, const int* in_sizes, int n_in,
                              void* d_out, int out_size)
{
    const float* x  = (const float*)d_in[0];
    const float* wq = (const float*)d_in[1];
    const float* wk = (const float*)d_in[2];
    const float* wv = (const float*)d_in[3];
    const float* wo = (const float*)d_in[4];
    float* out = (float*)d_out;

    cudaFuncSetAttribute(qkv_mma_kernel, cudaFuncAttributeMaxDynamicSharedMemorySize,
                         GEMM_SMEM);
    cudaFuncSetAttribute(proj_mma_kernel, cudaFuncAttributeMaxDynamicSharedMemorySize,
                         GEMM_SMEM);
    cudaFuncSetAttribute(attn_mma_kernel, cudaFuncAttributeMaxDynamicSharedMemorySize,
                         ATTN_SMEM);

    const int nx4 = MTOT * HIDDEN / 4;
    const int nw4 = HIDDEN * HIDDEN / 4;

    split_x_kernel<<<(nx4 + 255) / 256, 256>>>(x);
    dim3 gsw((nw4 + 255) / 256, 4);
    split_w_kernel<<<gsw, 256>>>(wq, wk, wv, wo);

    dim3 gqkv(HIDDEN / 256, MTOT / 128, 3);    // (3, 64, 3)
    qkv_mma_kernel<<<gqkv, 256, GEMM_SMEM>>>();

    dim3 gattn(SEQ / 64, BATCH * NH);          // (32, 48)
    attn_mma_kernel<<<gattn, 128, ATTN_SMEM>>>();

    dim3 gproj(HIDDEN / 256, MTOT / 128);      // (3, 64)
    proj_mma_kernel<<<gproj, 256, GEMM_SMEM>>>(out);
}

// round 15
// speedup vs baseline: 1.1084x; 1.1084x over previous
#include <cuda_runtime.h>
#include <cuda_bf16.h>
#include <math_constants.h>
#include <cstdint>

#define HIDDEN 768
#define NH     12
#define DH     64
#define BATCH  4
#define SEQ    2048
#define MTOT   (BATCH*SEQ)   // 8192

// ---------------------------------------------------------------------------
// Scratch (__device__ globals)
// ---------------------------------------------------------------------------
__device__ __nv_bfloat16 g_xhi[(size_t)MTOT * HIDDEN];
__device__ __nv_bfloat16 g_xlo[(size_t)MTOT * HIDDEN];
__device__ __nv_bfloat16 g_whi[4][(size_t)HIDDEN * HIDDEN];
__device__ __nv_bfloat16 g_wlo[4][(size_t)HIDDEN * HIDDEN];
__device__ __nv_bfloat16 g_qhi[(size_t)MTOT * HIDDEN];
__device__ __nv_bfloat16 g_qlo[(size_t)MTOT * HIDDEN];
__device__ __nv_bfloat16 g_khi[(size_t)MTOT * HIDDEN];
__device__ __nv_bfloat16 g_klo[(size_t)MTOT * HIDDEN];
__device__ __nv_bfloat16 g_vhi[(size_t)MTOT * HIDDEN];
__device__ __nv_bfloat16 g_vlo[(size_t)MTOT * HIDDEN];
__device__ __nv_bfloat16 g_chi[(size_t)MTOT * HIDDEN];
__device__ __nv_bfloat16 g_clo[(size_t)MTOT * HIDDEN];

// ---------------------------------------------------------------------------
// PTX primitives (baseline PTX only — valid on compute_103 target)
// ---------------------------------------------------------------------------
__device__ __forceinline__ uint32_t smem_u32(const void* p) {
    uint32_t a;
    asm("{ .reg .u64 t; cvta.to.shared.u64 t, %1; cvt.u32.u64 %0, t; }"
        : "=r"(a) : "l"(p));
    return a;
}

__device__ __forceinline__ void mma_bf16(float* d, const uint32_t* a, const uint32_t* b) {
    asm volatile(
        "mma.sync.aligned.m16n8k16.row.col.f32.bf16.bf16.f32 "
        "{%0,%1,%2,%3}, {%4,%5,%6,%7}, {%8,%9}, {%0,%1,%2,%3};"
        : "+f"(d[0]), "+f"(d[1]), "+f"(d[2]), "+f"(d[3])
        : "r"(a[0]), "r"(a[1]), "r"(a[2]), "r"(a[3]), "r"(b[0]), "r"(b[1]));
}

__device__ __forceinline__ void ldsm_x4(uint32_t* r, uint32_t addr) {
    asm volatile("ldmatrix.sync.aligned.m8n8.x4.shared.b16 {%0,%1,%2,%3}, [%4];"
                 : "=r"(r[0]), "=r"(r[1]), "=r"(r[2]), "=r"(r[3]) : "r"(addr));
}
__device__ __forceinline__ void ldsm_x4_t(uint32_t* r, uint32_t addr) {
    asm volatile("ldmatrix.sync.aligned.m8n8.x4.trans.shared.b16 {%0,%1,%2,%3}, [%4];"
                 : "=r"(r[0]), "=r"(r[1]), "=r"(r[2]), "=r"(r[3]) : "r"(addr));
}

__device__ __forceinline__ void cp_async16(uint32_t dst, const void* src) {
    asm volatile(
        "{ .reg .u64 g; cvta.to.global.u64 g, %1; "
        "cp.async.cg.shared.global [%0], [g], 16; }"
        :: "r"(dst), "l"(src));
}
#define CP_COMMIT() asm volatile("cp.async.commit_group;" ::: "memory")
#define CP_WAIT(n)  asm volatile("cp.async.wait_group %0;" :: "n"(n) : "memory")

__device__ __forceinline__ uint32_t bfpack(__nv_bfloat16 a, __nv_bfloat16 b) {
    __nv_bfloat162 t; t.x = a; t.y = b;
    return *(uint32_t*)&t;
}
__device__ __forceinline__ void split2(float a, float b, uint32_t& hi, uint32_t& lo) {
    __nv_bfloat16 ha = __float2bfloat16(a), hb = __float2bfloat16(b);
    __nv_bfloat16 la = __float2bfloat16(a - __bfloat162float(ha));
    __nv_bfloat16 lb = __float2bfloat16(b - __bfloat162float(hb));
    hi = bfpack(ha, hb);
    lo = bfpack(la, lb);
}

// ---------------------------------------------------------------------------
// fp32 -> bf16 hi/lo split kernels
// ---------------------------------------------------------------------------
__device__ __forceinline__ void split_body(const float* __restrict__ src,
                                           __nv_bfloat16* __restrict__ hi,
                                           __nv_bfloat16* __restrict__ lo, int i)
{
    float4 v = ((const float4*)src)[i];
    uint32_t h0, l0, h1, l1;
    split2(v.x, v.y, h0, l0);
    split2(v.z, v.w, h1, l1);
    ((uint32_t*)hi)[2 * i + 0] = h0;
    ((uint32_t*)hi)[2 * i + 1] = h1;
    ((uint32_t*)lo)[2 * i + 0] = l0;
    ((uint32_t*)lo)[2 * i + 1] = l1;
}

__global__ __launch_bounds__(256) void split_x_kernel(const float* __restrict__ src)
{
    int i = blockIdx.x * blockDim.x + threadIdx.x;
    if (i < MTOT * HIDDEN / 4) split_body(src, g_xhi, g_xlo, i);
}

__global__ __launch_bounds__(256) void split_w_kernel(const float* __restrict__ w0,
                                                      const float* __restrict__ w1,
                                                      const float* __restrict__ w2,
                                                      const float* __restrict__ w3)
{
    int z = blockIdx.y;
    const float* src = (z == 0) ? w0 : (z == 1) ? w1 : (z == 2) ? w2 : w3;
    int i = blockIdx.x * blockDim.x + threadIdx.x;
    if (i < HIDDEN * HIDDEN / 4) split_body(src, g_whi[z], g_wlo[z], i);
}

// ---------------------------------------------------------------------------
// HMMA bf16-split GEMM core (exact round-10 config: 128x128, 2-stage).
// 256 threads, 8 warps (2x4), warp tile 64x32.
// Buffer 32KB: Ah 0, Al 8192, Bh 16384, Bl 24576. 2 buffers = 64KB.
// Swizzle: chunk c ^ ((row>>1)&3).
// ---------------------------------------------------------------------------
#define KCH (HIDDEN / 32)    // 24
#define GEMM_SMEM 65536

extern __shared__ uint4 dynsm[];

struct GemmFrag {
    float acc[4][4][4];
    int lane, wm, wn;
};

__device__ __forceinline__ void hmma_core(const __nv_bfloat16* __restrict__ Ahi,
                                          const __nv_bfloat16* __restrict__ Alo,
                                          const __nv_bfloat16* __restrict__ Bhi,
                                          const __nv_bfloat16* __restrict__ Blo,
                                          int bm, int bn, GemmFrag& fr)
{
    const uint32_t sb = smem_u32(dynsm);

    const int tid  = threadIdx.x;
    const int lane = tid & 31;
    const int wid  = tid >> 5;
    fr.lane = lane;
    fr.wm   = (wid & 1) * 64;
    fr.wn   = (wid >> 1) * 32;

    const int r0 = tid >> 2;
    const int c0 = tid & 3;
    const uint32_t dst0 = (uint32_t)(r0 * 4 + (c0 ^ ((r0 >> 1) & 3))) * 16;
    const uint32_t dst1 = dst0 + 4096;

    const uint4* Ah4 = (const uint4*)Ahi;
    const uint4* Al4 = (const uint4*)Alo;
    const uint4* Bh4 = (const uint4*)Bhi;
    const uint4* Bl4 = (const uint4*)Blo;
    const int rowstride4 = HIDDEN / 8;
    const size_t srcA0 = (size_t)(bm + r0) * rowstride4 + c0;
    const size_t srcA1 = (size_t)(bm + r0 + 64) * rowstride4 + c0;
    const size_t srcB0 = (size_t)(bn + r0) * rowstride4 + c0;
    const size_t srcB1 = (size_t)(bn + r0 + 64) * rowstride4 + c0;

    uint32_t offA[2][4], offB[2][2];
#pragma unroll
    for (int mi = 0; mi < 4; mi++) {
        int rowA = fr.wm + mi * 16 + (lane & 15);
        int keyA = (rowA >> 1) & 3;
#pragma unroll
        for (int ks = 0; ks < 2; ks++) {
            int c = ks * 2 + (lane >> 4);
            offA[ks][mi] = rowA * 64 + ((c ^ keyA) << 4);
        }
    }
#pragma unroll
    for (int p = 0; p < 2; p++) {       // ni pair: (2p, 2p+1)
        int rowB = fr.wn + (2 * p + ((lane >> 4) & 1)) * 8 + (lane & 7);
        int keyB = (rowB >> 1) & 3;
#pragma unroll
        for (int ks = 0; ks < 2; ks++) {
            int c = ks * 2 + ((lane >> 3) & 1);
            offB[ks][p] = rowB * 64 + ((c ^ keyB) << 4);
        }
    }

#pragma unroll
    for (int mi = 0; mi < 4; mi++)
#pragma unroll
        for (int ni = 0; ni < 4; ni++)
#pragma unroll
            for (int t = 0; t < 4; t++) fr.acc[mi][ni][t] = 0.0f;

    auto stage = [&](int kc, int buf) {
        const size_t ko = (size_t)kc * 4;
        uint32_t d = sb + (uint32_t)buf * 32768;
        cp_async16(d + dst0,         Ah4 + srcA0 + ko);
        cp_async16(d + dst1,         Ah4 + srcA1 + ko);
        cp_async16(d + 8192 + dst0,  Al4 + srcA0 + ko);
        cp_async16(d + 8192 + dst1,  Al4 + srcA1 + ko);
        cp_async16(d + 16384 + dst0, Bh4 + srcB0 + ko);
        cp_async16(d + 16384 + dst1, Bh4 + srcB1 + ko);
        cp_async16(d + 24576 + dst0, Bl4 + srcB0 + ko);
        cp_async16(d + 24576 + dst1, Bl4 + srcB1 + ko);
    };

    stage(0, 0);
    CP_COMMIT();

    for (int kc = 0; kc < KCH; kc++) {
        if (kc + 1 < KCH) {
            stage(kc + 1, (kc + 1) & 1);
            CP_COMMIT();
            CP_WAIT(1);
        } else {
            CP_WAIT(0);
        }
        __syncthreads();

        const uint32_t bAh = sb + (uint32_t)(kc & 1) * 32768;
        const uint32_t bAl = bAh + 8192;
        const uint32_t bBh = bAh + 16384;
        const uint32_t bBl = bAh + 24576;

#pragma unroll
        for (int ks = 0; ks < 2; ks++) {
            uint32_t ah[4][4], al[4][4], bh[2][4], bl[2][4];
#pragma unroll
            for (int mi = 0; mi < 4; mi++) {
                ldsm_x4(ah[mi], bAh + offA[ks][mi]);
                ldsm_x4(al[mi], bAl + offA[ks][mi]);
            }
#pragma unroll
            for (int p = 0; p < 2; p++) {
                ldsm_x4(bh[p], bBh + offB[ks][p]);
                ldsm_x4(bl[p], bBl + offB[ks][p]);
            }
            // term-outer ordering: RAW dep distance = 16
#pragma unroll
            for (int mi = 0; mi < 4; mi++)
#pragma unroll
                for (int ni = 0; ni < 4; ni++)
                    mma_bf16(fr.acc[mi][ni], ah[mi], &bh[ni >> 1][(ni & 1) * 2]);
#pragma unroll
            for (int mi = 0; mi < 4; mi++)
#pragma unroll
                for (int ni = 0; ni < 4; ni++)
                    mma_bf16(fr.acc[mi][ni], ah[mi], &bl[ni >> 1][(ni & 1) * 2]);
#pragma unroll
            for (int mi = 0; mi < 4; mi++)
#pragma unroll
                for (int ni = 0; ni < 4; ni++)
                    mma_bf16(fr.acc[mi][ni], al[mi], &bh[ni >> 1][(ni & 1) * 2]);
        }
        __syncthreads();
    }
}

// qkv: epilogue writes bf16 hi/lo (Q pre-scaled by 1/8)
__global__ __launch_bounds__(256) void qkv_mma_kernel()
{
    const int z = blockIdx.z;
    __nv_bfloat16 *Ohi, *Olo;
    float scale;
    if (z == 0)      { Ohi = g_qhi; Olo = g_qlo; scale = 0.125f; }
    else if (z == 1) { Ohi = g_khi; Olo = g_klo; scale = 1.0f; }
    else             { Ohi = g_vhi; Olo = g_vlo; scale = 1.0f; }

    GemmFrag fr;
    hmma_core(g_xhi, g_xlo, g_whi[z], g_wlo[z], blockIdx.y * 128, blockIdx.x * 128, fr);

    const int bm = blockIdx.y * 128, bn = blockIdx.x * 128;
#pragma unroll
    for (int mi = 0; mi < 4; mi++) {
        int row = bm + fr.wm + mi * 16 + (fr.lane >> 2);
#pragma unroll
        for (int ni = 0; ni < 4; ni++) {
            int col = bn + fr.wn + ni * 8 + ((fr.lane & 3) << 1);
            uint32_t h0, l0, h1, l1;
            split2(fr.acc[mi][ni][0] * scale, fr.acc[mi][ni][1] * scale, h0, l0);
            split2(fr.acc[mi][ni][2] * scale, fr.acc[mi][ni][3] * scale, h1, l1);
            *(uint32_t*)(Ohi + (size_t)row * HIDDEN + col) = h0;
            *(uint32_t*)(Olo + (size_t)row * HIDDEN + col) = l0;
            *(uint32_t*)(Ohi + (size_t)(row + 8) * HIDDEN + col) = h1;
            *(uint32_t*)(Olo + (size_t)(row + 8) * HIDDEN + col) = l1;
        }
    }
}

// proj: fp32 out
__global__ __launch_bounds__(256) void proj_mma_kernel(float* __restrict__ out)
{
    GemmFrag fr;
    hmma_core(g_chi, g_clo, g_whi[3], g_wlo[3], blockIdx.y * 128, blockIdx.x * 128, fr);

    const int bm = blockIdx.y * 128, bn = blockIdx.x * 128;
#pragma unroll
    for (int mi = 0; mi < 4; mi++) {
        int row = bm + fr.wm + mi * 16 + (fr.lane >> 2);
#pragma unroll
        for (int ni = 0; ni < 4; ni++) {
            int col = bn + fr.wn + ni * 8 + ((fr.lane & 3) << 1);
            *(float2*)(out + (size_t)row * HIDDEN + col) =
                make_float2(fr.acc[mi][ni][0], fr.acc[mi][ni][1]);
            *(float2*)(out + (size_t)(row + 8) * HIDDEN + col) =
                make_float2(fr.acc[mi][ni][2], fr.acc[mi][ni][3]);
        }
    }
}

// ---------------------------------------------------------------------------
// Tensor-core flash attention, warp M-tile = 32 q-rows.
// CTA: 128 q x one (b,h), 4 warps (warp = rows wid*32..wid*32+31, 2 m-tiles).
// K/V fragments reused across both m-tiles: LDSM per MMA halved vs r10.
// cp.async double-buffered KV. Buffer (32KB): Khi 0, Klo 8192, Vhi 16384,
// Vlo 24576. Q staged once (32KB: hi 0, lo 16384). Swizzle c ^ (row&7).
// ---------------------------------------------------------------------------
#define ATTN_SMEM 65536

__global__ __launch_bounds__(128, 2) void attn_mma_kernel()
{
    const uint32_t sb = smem_u32(dynsm);

    const int tid  = threadIdx.x;
    const int lane = tid & 31;
    const int wid  = tid >> 5;          // 0..3
    const int bh   = blockIdx.y;
    const int b    = bh / NH;
    const int h    = bh % NH;
    const int q0   = blockIdx.x * 128;

    const size_t base = (size_t)b * SEQ * HIDDEN + h * DH;

    // ---- stage Q (128 rows; hi at 0, lo at 16384) ----
#pragma unroll
    for (int j = 0; j < 8; j++) {
        int idx = j * 128 + tid;
        int r = idx >> 3, c = idx & 7;
        uint32_t d = (uint32_t)(r * 8 + (c ^ (r & 7))) * 16;
        cp_async16(sb + d,         (const uint4*)(g_qhi + base + (size_t)(q0 + r) * HIDDEN) + c);
        cp_async16(sb + 16384 + d, (const uint4*)(g_qlo + base + (size_t)(q0 + r) * HIDDEN) + c);
    }
    CP_COMMIT();
    CP_WAIT(0);
    __syncthreads();

    // ---- Q fragments: 2 m-tiles x 4 k-steps (held for whole kernel) ----
    uint32_t qh[2][4][4], ql[2][4][4];
#pragma unroll
    for (int mt = 0; mt < 2; mt++) {
        int qrow = wid * 32 + mt * 16 + (lane & 15);
        int key  = qrow & 7;
#pragma unroll
        for (int ks = 0; ks < 4; ks++) {
            int c = ks * 2 + (lane >> 4);
            uint32_t off = (uint32_t)(qrow * 8 + (c ^ key)) * 16;
            ldsm_x4(qh[mt][ks], sb + off);
            ldsm_x4(ql[mt][ks], sb + 16384 + off);
        }
    }
    __syncthreads();

    float accO[2][8][4];
#pragma unroll
    for (int mt = 0; mt < 2; mt++)
#pragma unroll
        for (int n = 0; n < 8; n++)
#pragma unroll
            for (int t = 0; t < 4; t++) accO[mt][n][t] = 0.0f;
    float m_[2][2] = {{-CUDART_INF_F, -CUDART_INF_F}, {-CUDART_INF_F, -CUDART_INF_F}};
    float l_[2][2] = {{0.0f, 0.0f}, {0.0f, 0.0f}};

    // KV staging: 64 key rows x 8 chunks x 4 arrays, 128 threads -> 16/thread
    const int sr = tid >> 3;           // 0..15
    const int sc = tid & 7;
    uint32_t sd[4];
#pragma unroll
    for (int u = 0; u < 4; u++) {
        int row = sr + u * 16;
        sd[u] = (uint32_t)(row * 8 + (sc ^ (row & 7))) * 16;
    }

    auto stageKV = [&](int kt, int buf) {
        uint32_t d = sb + (uint32_t)buf * 32768;
#pragma unroll
        for (int u = 0; u < 4; u++) {
            size_t roff = base + (size_t)(kt + sr + u * 16) * HIDDEN;
            cp_async16(d + sd[u],         (const uint4*)(g_khi + roff) + sc);
            cp_async16(d + 8192 + sd[u],  (const uint4*)(g_klo + roff) + sc);
            cp_async16(d + 16384 + sd[u], (const uint4*)(g_vhi + roff) + sc);
            cp_async16(d + 24576 + sd[u], (const uint4*)(g_vlo + roff) + sc);
        }
    };

    stageKV(0, 0);
    CP_COMMIT();

    for (int it = 0; it < SEQ / 64; it++) {
        if (it + 1 < SEQ / 64) {
            stageKV((it + 1) * 64, (it + 1) & 1);
            CP_COMMIT();
            CP_WAIT(1);
        } else {
            CP_WAIT(0);
        }
        __syncthreads();

        const uint32_t bKh = sb + (uint32_t)(it & 1) * 32768;
        const uint32_t bKl = bKh + 8192;
        const uint32_t bVh = bKh + 16384;
        const uint32_t bVl = bKh + 24576;

        // ---- S = Q.K^T (3-term), K fragments shared across both m-tiles ----
        float s[2][8][4];
#pragma unroll
        for (int mt = 0; mt < 2; mt++)
#pragma unroll
            for (int n = 0; n < 8; n++)
#pragma unroll
                for (int t = 0; t < 4; t++) s[mt][n][t] = 0.0f;

#pragma unroll
        for (int ks = 0; ks < 4; ks++) {
#pragma unroll
            for (int pp = 0; pp < 4; pp += 2) {
                uint32_t kh4[2][4], kl4[2][4];
#pragma unroll
                for (int d2 = 0; d2 < 2; d2++) {
                    int p = pp + d2;
                    int krow = (2 * p + ((lane >> 4) & 1)) * 8 + (lane & 7);
                    int c = ks * 2 + ((lane >> 3) & 1);
                    uint32_t off = (uint32_t)(krow * 8 + (c ^ (lane & 7))) * 16;
                    ldsm_x4(kh4[d2], bKh + off);
                    ldsm_x4(kl4[d2], bKl + off);
                }
                // term-grouped: 8 independent accumulators per term pass
#pragma unroll
                for (int mt = 0; mt < 2; mt++)
#pragma unroll
                    for (int d2 = 0; d2 < 2; d2++) {
                        mma_bf16(s[mt][2 * (pp + d2) + 0], qh[mt][ks], &kh4[d2][0]);
                        mma_bf16(s[mt][2 * (pp + d2) + 1], qh[mt][ks], &kh4[d2][2]);
                    }
#pragma unroll
                for (int mt = 0; mt < 2; mt++)
#pragma unroll
                    for (int d2 = 0; d2 < 2; d2++) {
                        mma_bf16(s[mt][2 * (pp + d2) + 0], qh[mt][ks], &kl4[d2][0]);
                        mma_bf16(s[mt][2 * (pp + d2) + 1], qh[mt][ks], &kl4[d2][2]);
                    }
#pragma unroll
                for (int mt = 0; mt < 2; mt++)
#pragma unroll
                    for (int d2 = 0; d2 < 2; d2++) {
                        mma_bf16(s[mt][2 * (pp + d2) + 0], ql[mt][ks], &kh4[d2][0]);
                        mma_bf16(s[mt][2 * (pp + d2) + 1], ql[mt][ks], &kh4[d2][2]);
                    }
            }
        }

        // ---- online softmax per m-tile (rows lane>>2 and +8) ----
#pragma unroll
        for (int mt = 0; mt < 2; mt++) {
            float rmax0 = -CUDART_INF_F, rmax1 = -CUDART_INF_F;
#pragma unroll
            for (int n = 0; n < 8; n++) {
                rmax0 = fmaxf(rmax0, fmaxf(s[mt][n][0], s[mt][n][1]));
                rmax1 = fmaxf(rmax1, fmaxf(s[mt][n][2], s[mt][n][3]));
            }
            rmax0 = fmaxf(rmax0, __shfl_xor_sync(0xffffffffu, rmax0, 1));
            rmax0 = fmaxf(rmax0, __shfl_xor_sync(0xffffffffu, rmax0, 2));
            rmax1 = fmaxf(rmax1, __shfl_xor_sync(0xffffffffu, rmax1, 1));
            rmax1 = fmaxf(rmax1, __shfl_xor_sync(0xffffffffu, rmax1, 2));
            float mn0 = fmaxf(m_[mt][0], rmax0), mn1 = fmaxf(m_[mt][1], rmax1);
            float a0 = __expf(m_[mt][0] - mn0), a1 = __expf(m_[mt][1] - mn1);
            float sum0 = 0.0f, sum1 = 0.0f;
#pragma unroll
            for (int n = 0; n < 8; n++) {
                s[mt][n][0] = __expf(s[mt][n][0] - mn0);
                s[mt][n][1] = __expf(s[mt][n][1] - mn0);
                s[mt][n][2] = __expf(s[mt][n][2] - mn1);
                s[mt][n][3] = __expf(s[mt][n][3] - mn1);
                sum0 += s[mt][n][0] + s[mt][n][1];
                sum1 += s[mt][n][2] + s[mt][n][3];
            }
            sum0 += __shfl_xor_sync(0xffffffffu, sum0, 1);
            sum0 += __shfl_xor_sync(0xffffffffu, sum0, 2);
            sum1 += __shfl_xor_sync(0xffffffffu, sum1, 1);
            sum1 += __shfl_xor_sync(0xffffffffu, sum1, 2);
            l_[mt][0] = l_[mt][0] * a0 + sum0;
            l_[mt][1] = l_[mt][1] * a1 + sum1;
            m_[mt][0] = mn0; m_[mt][1] = mn1;
#pragma unroll
            for (int n = 0; n < 8; n++) {
                accO[mt][n][0] *= a0; accO[mt][n][1] *= a0;
                accO[mt][n][2] *= a1; accO[mt][n][3] *= a1;
            }
        }

        // ---- O += P.V (3-term); V fragments shared across m-tiles ----
#pragma unroll
        for (int j = 0; j < 4; j++) {
            uint32_t ph[2][4], pl[2][4];
#pragma unroll
            for (int mt = 0; mt < 2; mt++) {
                split2(s[mt][2 * j][0],     s[mt][2 * j][1],     ph[mt][0], pl[mt][0]);
                split2(s[mt][2 * j][2],     s[mt][2 * j][3],     ph[mt][1], pl[mt][1]);
                split2(s[mt][2 * j + 1][0], s[mt][2 * j + 1][1], ph[mt][2], pl[mt][2]);
                split2(s[mt][2 * j + 1][2], s[mt][2 * j + 1][3], ph[mt][3], pl[mt][3]);
            }
            int vrow = j * 16 + (lane & 15);
#pragma unroll
            for (int qq = 0; qq < 4; qq += 2) {
                uint32_t vh4[2][4], vl4[2][4];
#pragma unroll
                for (int d2 = 0; d2 < 2; d2++) {
                    int c = 2 * (qq + d2) + ((lane >> 4) & 1);
                    uint32_t off = (uint32_t)(vrow * 8 + (c ^ (vrow & 7))) * 16;
                    ldsm_x4_t(vh4[d2], bVh + off);
                    ldsm_x4_t(vl4[d2], bVl + off);
                }
#pragma unroll
                for (int mt = 0; mt < 2; mt++)
#pragma unroll
                    for (int d2 = 0; d2 < 2; d2++) {
                        mma_bf16(accO[mt][2 * (qq + d2) + 0], ph[mt], &vh4[d2][0]);
                        mma_bf16(accO[mt][2 * (qq + d2) + 1], ph[mt], &vh4[d2][2]);
                    }
#pragma unroll
                for (int mt = 0; mt < 2; mt++)
#pragma unroll
                    for (int d2 = 0; d2 < 2; d2++) {
                        mma_bf16(accO[mt][2 * (qq + d2) + 0], ph[mt], &vl4[d2][0]);
                        mma_bf16(accO[mt][2 * (qq + d2) + 1], ph[mt], &vl4[d2][2]);
                    }
#pragma unroll
                for (int mt = 0; mt < 2; mt++)
#pragma unroll
                    for (int d2 = 0; d2 < 2; d2++) {
                        mma_bf16(accO[mt][2 * (qq + d2) + 0], pl[mt], &vh4[d2][0]);
                        mma_bf16(accO[mt][2 * (qq + d2) + 1], pl[mt], &vh4[d2][2]);
                    }
            }
        }
        __syncthreads();
    }

    // ---- epilogue: normalize, write ctx hi/lo bf16 ----
#pragma unroll
    for (int mt = 0; mt < 2; mt++) {
        float inv0 = 1.0f / l_[mt][0], inv1 = 1.0f / l_[mt][1];
        int row = q0 + wid * 32 + mt * 16 + (lane >> 2);
#pragma unroll
        for (int n2 = 0; n2 < 8; n2++) {
            int col = n2 * 8 + ((lane & 3) << 1);
            uint32_t h0, lo0, h1, lo1;
            split2(accO[mt][n2][0] * inv0, accO[mt][n2][1] * inv0, h0, lo0);
            split2(accO[mt][n2][2] * inv1, accO[mt][n2][3] * inv1, h1, lo1);
            size_t p0 = base + (size_t)row * HIDDEN + col;
            size_t p1 = base + (size_t)(row + 8) * HIDDEN + col;
            *(uint32_t*)(g_chi + p0) = h0;
            *(uint32_t*)(g_clo + p0) = lo0;
            *(uint32_t*)(g_chi + p1) = h1;
            *(uint32_t*)(g_clo + p1) = lo1;
        }
    }
}

// ---------------------------------------------------------------------------
extern "C" void kernel_launch(void* const* d_in, const int* in_sizes, int n_in,
                              void* d_out, int out_size)
{
    const float* x  = (const float*)d_in[0];
    const float* wq = (const float*)d_in[1];
    const float* wk = (const float*)d_in[2];
    const float* wv = (const float*)d_in[3];
    const float* wo = (const float*)d_in[4];
    float* out = (float*)d_out;

    cudaFuncSetAttribute(qkv_mma_kernel, cudaFuncAttributeMaxDynamicSharedMemorySize,
                         GEMM_SMEM);
    cudaFuncSetAttribute(proj_mma_kernel, cudaFuncAttributeMaxDynamicSharedMemorySize,
                         GEMM_SMEM);
    cudaFuncSetAttribute(attn_mma_kernel, cudaFuncAttributeMaxDynamicSharedMemorySize,
                         ATTN_SMEM);

    const int nx4 = MTOT * HIDDEN / 4;
    const int nw4 = HIDDEN * HIDDEN / 4;

    split_x_kernel<<<(nx4 + 255) / 256, 256>>>(x);
    dim3 gsw((nw4 + 255) / 256, 4);
    split_w_kernel<<<gsw, 256>>>(wq, wk, wv, wo);

    dim3 gqkv(HIDDEN / 128, MTOT / 128, 3);    // (6, 64, 3)
    qkv_mma_kernel<<<gqkv, 256, GEMM_SMEM>>>();

    dim3 gattn(SEQ / 128, BATCH * NH);         // (16, 48)
    attn_mma_kernel<<<gattn, 128, ATTN_SMEM>>>();

    dim3 gproj(HIDDEN / 128, MTOT / 128);      // (6, 64)
    proj_mma_kernel<<<gproj, 256, GEMM_SMEM>>>(out);
}

// round 17
// speedup vs baseline: 1.7653x; 1.5927x over previous
#include <cuda_runtime.h>
#include <cuda_fp16.h>
#include <math_constants.h>
#include <cstdint>

#define HIDDEN 768
#define NH     12
#define DH     64
#define BATCH  4
#define SEQ    2048
#define MTOT   (BATCH*SEQ)   // 8192

// ---------------------------------------------------------------------------
// Scratch: one arena, carved by offsets (fp16; A-side split, B-side single)
// ---------------------------------------------------------------------------
#define NELEM ((size_t)MTOT * HIDDEN)          // 6291456
#define WELEM ((size_t)HIDDEN * HIDDEN)        // 589824
__device__ __half g_arena[9 * NELEM + 4 * WELEM];

#define g_xhi (g_arena + 0 * NELEM)
#define g_xlo (g_arena + 1 * NELEM)
#define g_qhi (g_arena + 2 * NELEM)
#define g_qlo (g_arena + 3 * NELEM)
#define g_k   (g_arena + 4 * NELEM)
#define g_v   (g_arena + 5 * NELEM)
#define g_chi (g_arena + 6 * NELEM)
#define g_clo (g_arena + 7 * NELEM)
#define g_w(z) (g_arena + 8 * NELEM + (size_t)(z) * WELEM)

// ---------------------------------------------------------------------------
// PTX primitives (baseline PTX only — valid on compute_103 target)
// ---------------------------------------------------------------------------
__device__ __forceinline__ uint32_t smem_u32(const void* p) {
    uint32_t a;
    asm("{ .reg .u64 t; cvta.to.shared.u64 t, %1; cvt.u32.u64 %0, t; }"
        : "=r"(a) : "l"(p));
    return a;
}

__device__ __forceinline__ void mma_f16(float* d, const uint32_t* a, const uint32_t* b) {
    asm volatile(
        "mma.sync.aligned.m16n8k16.row.col.f32.f16.f16.f32 "
        "{%0,%1,%2,%3}, {%4,%5,%6,%7}, {%8,%9}, {%0,%1,%2,%3};"
        : "+f"(d[0]), "+f"(d[1]), "+f"(d[2]), "+f"(d[3])
        : "r"(a[0]), "r"(a[1]), "r"(a[2]), "r"(a[3]), "r"(b[0]), "r"(b[1]));
}

__device__ __forceinline__ void ldsm_x4(uint32_t* r, uint32_t addr) {
    asm volatile("ldmatrix.sync.aligned.m8n8.x4.shared.b16 {%0,%1,%2,%3}, [%4];"
                 : "=r"(r[0]), "=r"(r[1]), "=r"(r[2]), "=r"(r[3]) : "r"(addr));
}
__device__ __forceinline__ void ldsm_x4_t(uint32_t* r, uint32_t addr) {
    asm volatile("ldmatrix.sync.aligned.m8n8.x4.trans.shared.b16 {%0,%1,%2,%3}, [%4];"
                 : "=r"(r[0]), "=r"(r[1]), "=r"(r[2]), "=r"(r[3]) : "r"(addr));
}

__device__ __forceinline__ void cp_async16(uint32_t dst, const void* src) {
    asm volatile(
        "{ .reg .u64 g; cvta.to.global.u64 g, %1; "
        "cp.async.cg.shared.global [%0], [g], 16; }"
        :: "r"(dst), "l"(src));
}
#define CP_COMMIT() asm volatile("cp.async.commit_group;" ::: "memory")
#define CP_WAIT(n)  asm volatile("cp.async.wait_group %0;" :: "n"(n) : "memory")

__device__ __forceinline__ uint32_t hpack(__half a, __half b) {
    __half2 t; t.x = a; t.y = b;
    return *(uint32_t*)&t;
}
// fp16 hi/lo split: x = hi + lo + O(2^-23 x)
__device__ __forceinline__ void hsplit2(float a, float b, uint32_t& hi, uint32_t& lo) {
    __half ha = __float2half_rn(a), hb = __float2half_rn(b);
    __half la = __float2half_rn(a - __half2float(ha));
    __half lb = __float2half_rn(b - __half2float(hb));
    hi = hpack(ha, hb);
    lo = hpack(la, lb);
}

// ---------------------------------------------------------------------------
// fp32 -> fp16 split / convert kernels
// ---------------------------------------------------------------------------
__global__ __launch_bounds__(256) void split_x_kernel(const float* __restrict__ src)
{
    int i = blockIdx.x * blockDim.x + threadIdx.x;
    if (i >= (int)(NELEM / 4)) return;
    float4 v = ((const float4*)src)[i];
    uint32_t h0, l0, h1, l1;
    hsplit2(v.x, v.y, h0, l0);
    hsplit2(v.z, v.w, h1, l1);
    ((uint32_t*)g_xhi)[2 * i + 0] = h0;
    ((uint32_t*)g_xhi)[2 * i + 1] = h1;
    ((uint32_t*)g_xlo)[2 * i + 0] = l0;
    ((uint32_t*)g_xlo)[2 * i + 1] = l1;
}

__global__ __launch_bounds__(256) void conv_w_kernel(const float* __restrict__ w0,
                                                     const float* __restrict__ w1,
                                                     const float* __restrict__ w2,
                                                     const float* __restrict__ w3)
{
    int z = blockIdx.y;
    const float* src = (z == 0) ? w0 : (z == 1) ? w1 : (z == 2) ? w2 : w3;
    int i = blockIdx.x * blockDim.x + threadIdx.x;
    if (i >= (int)(WELEM / 4)) return;
    float4 v = ((const float4*)src)[i];
    ((uint32_t*)g_w(z))[2 * i + 0] = hpack(__float2half_rn(v.x), __float2half_rn(v.y));
    ((uint32_t*)g_w(z))[2 * i + 1] = hpack(__float2half_rn(v.z), __float2half_rn(v.w));
}

// ---------------------------------------------------------------------------
// HMMA fp16 one-sided-split GEMM: C = (Ahi+Alo) @ B^T, 2 MMAs per product.
// 128x128 CTA, BK=32, 256 threads, 8 warps (2x4), warp tile 64x32.
// Buffer 24KB: Ah 0, Al 8192, B 16384. 2 buffers = 48KB. Swizzle c^((r>>1)&3).
// ---------------------------------------------------------------------------
#define KCH (HIDDEN / 32)    // 24
#define GEMM_BUF 24576
#define GEMM_SMEM (2 * GEMM_BUF)

extern __shared__ uint4 dynsm[];

struct GemmFrag {
    float acc[4][4][4];
    int lane, wm, wn;
};

__device__ __forceinline__ void hmma_core(const __half* __restrict__ Ahi,
                                          const __half* __restrict__ Alo,
                                          const __half* __restrict__ B,
                                          int bm, int bn, GemmFrag& fr)
{
    const uint32_t sb = smem_u32(dynsm);

    const int tid  = threadIdx.x;
    const int lane = tid & 31;
    const int wid  = tid >> 5;
    fr.lane = lane;
    fr.wm   = (wid & 1) * 64;
    fr.wn   = (wid >> 1) * 32;

    const int r0 = tid >> 2;
    const int c0 = tid & 3;
    const uint32_t dst0 = (uint32_t)(r0 * 4 + (c0 ^ ((r0 >> 1) & 3))) * 16;
    const uint32_t dst1 = dst0 + 4096;

    const uint4* Ah4 = (const uint4*)Ahi;
    const uint4* Al4 = (const uint4*)Alo;
    const uint4* B4  = (const uint4*)B;
    const int rowstride4 = HIDDEN / 8;
    const size_t srcA0 = (size_t)(bm + r0) * rowstride4 + c0;
    const size_t srcA1 = (size_t)(bm + r0 + 64) * rowstride4 + c0;
    const size_t srcB0 = (size_t)(bn + r0) * rowstride4 + c0;
    const size_t srcB1 = (size_t)(bn + r0 + 64) * rowstride4 + c0;

    uint32_t offA[2][4], offB[2][2];
#pragma unroll
    for (int mi = 0; mi < 4; mi++) {
        int rowA = fr.wm + mi * 16 + (lane & 15);
        int keyA = (rowA >> 1) & 3;
#pragma unroll
        for (int ks = 0; ks < 2; ks++) {
            int c = ks * 2 + (lane >> 4);
            offA[ks][mi] = rowA * 64 + ((c ^ keyA) << 4);
        }
    }
#pragma unroll
    for (int p = 0; p < 2; p++) {       // ni pair: (2p, 2p+1)
        int rowB = fr.wn + (2 * p + ((lane >> 4) & 1)) * 8 + (lane & 7);
        int keyB = (rowB >> 1) & 3;
#pragma unroll
        for (int ks = 0; ks < 2; ks++) {
            int c = ks * 2 + ((lane >> 3) & 1);
            offB[ks][p] = rowB * 64 + ((c ^ keyB) << 4);
        }
    }

#pragma unroll
    for (int mi = 0; mi < 4; mi++)
#pragma unroll
        for (int ni = 0; ni < 4; ni++)
#pragma unroll
            for (int t = 0; t < 4; t++) fr.acc[mi][ni][t] = 0.0f;

    auto stage = [&](int kc, int buf) {
        const size_t ko = (size_t)kc * 4;
        uint32_t d = sb + (uint32_t)buf * GEMM_BUF;
        cp_async16(d + dst0,         Ah4 + srcA0 + ko);
        cp_async16(d + dst1,         Ah4 + srcA1 + ko);
        cp_async16(d + 8192 + dst0,  Al4 + srcA0 + ko);
        cp_async16(d + 8192 + dst1,  Al4 + srcA1 + ko);
        cp_async16(d + 16384 + dst0, B4 + srcB0 + ko);
        cp_async16(d + 16384 + dst1, B4 + srcB1 + ko);
    };

    stage(0, 0);
    CP_COMMIT();

    for (int kc = 0; kc < KCH; kc++) {
        if (kc + 1 < KCH) {
            stage(kc + 1, (kc + 1) & 1);
            CP_COMMIT();
            CP_WAIT(1);
        } else {
            CP_WAIT(0);
        }
        __syncthreads();

        const uint32_t bAh = sb + (uint32_t)(kc & 1) * GEMM_BUF;
        const uint32_t bAl = bAh + 8192;
        const uint32_t bB  = bAh + 16384;

#pragma unroll
        for (int ks = 0; ks < 2; ks++) {
            uint32_t ah[4][4], al[4][4], b[2][4];
#pragma unroll
            for (int mi = 0; mi < 4; mi++) {
                ldsm_x4(ah[mi], bAh + offA[ks][mi]);
                ldsm_x4(al[mi], bAl + offA[ks][mi]);
            }
#pragma unroll
            for (int p = 0; p < 2; p++)
                ldsm_x4(b[p], bB + offB[ks][p]);
            // term-outer ordering: RAW dep distance = 16
#pragma unroll
            for (int mi = 0; mi < 4; mi++)
#pragma unroll
                for (int ni = 0; ni < 4; ni++)
                    mma_f16(fr.acc[mi][ni], ah[mi], &b[ni >> 1][(ni & 1) * 2]);
#pragma unroll
            for (int mi = 0; mi < 4; mi++)
#pragma unroll
                for (int ni = 0; ni < 4; ni++)
                    mma_f16(fr.acc[mi][ni], al[mi], &b[ni >> 1][(ni & 1) * 2]);
        }
        __syncthreads();
    }
}

// qkv: Q written split hi/lo (scaled 1/8); K, V written single fp16
__global__ __launch_bounds__(256) void qkv_mma_kernel()
{
    const int z = blockIdx.z;

    GemmFrag fr;
    hmma_core(g_xhi, g_xlo, g_w(z), blockIdx.y * 128, blockIdx.x * 128, fr);

    const int bm = blockIdx.y * 128, bn = blockIdx.x * 128;
#pragma unroll
    for (int mi = 0; mi < 4; mi++) {
        int row = bm + fr.wm + mi * 16 + (fr.lane >> 2);
#pragma unroll
        for (int ni = 0; ni < 4; ni++) {
            int col = bn + fr.wn + ni * 8 + ((fr.lane & 3) << 1);
            size_t p0 = (size_t)row * HIDDEN + col;
            size_t p1 = (size_t)(row + 8) * HIDDEN + col;
            if (z == 0) {
                uint32_t h0, l0, h1, l1;
                hsplit2(fr.acc[mi][ni][0] * 0.125f, fr.acc[mi][ni][1] * 0.125f, h0, l0);
                hsplit2(fr.acc[mi][ni][2] * 0.125f, fr.acc[mi][ni][3] * 0.125f, h1, l1);
                *(uint32_t*)(g_qhi + p0) = h0;
                *(uint32_t*)(g_qlo + p0) = l0;
                *(uint32_t*)(g_qhi + p1) = h1;
                *(uint32_t*)(g_qlo + p1) = l1;
            } else {
                __half* O = (z == 1) ? g_k : g_v;
                *(uint32_t*)(O + p0) = hpack(__float2half_rn(fr.acc[mi][ni][0]),
                                             __float2half_rn(fr.acc[mi][ni][1]));
                *(uint32_t*)(O + p1) = hpack(__float2half_rn(fr.acc[mi][ni][2]),
                                             __float2half_rn(fr.acc[mi][ni][3]));
            }
        }
    }
}

// proj: fp32 out
__global__ __launch_bounds__(256) void proj_mma_kernel(float* __restrict__ out)
{
    GemmFrag fr;
    hmma_core(g_chi, g_clo, g_w(3), blockIdx.y * 128, blockIdx.x * 128, fr);

    const int bm = blockIdx.y * 128, bn = blockIdx.x * 128;
#pragma unroll
    for (int mi = 0; mi < 4; mi++) {
        int row = bm + fr.wm + mi * 16 + (fr.lane >> 2);
#pragma unroll
        for (int ni = 0; ni < 4; ni++) {
            int col = bn + fr.wn + ni * 8 + ((fr.lane & 3) << 1);
            *(float2*)(out + (size_t)row * HIDDEN + col) =
                make_float2(fr.acc[mi][ni][0], fr.acc[mi][ni][1]);
            *(float2*)(out + (size_t)(row + 8) * HIDDEN + col) =
                make_float2(fr.acc[mi][ni][2], fr.acc[mi][ni][3]);
        }
    }
}

// ---------------------------------------------------------------------------
// Tensor-core flash attention, fp16 one-sided split (Q,P split; K,V single).
// 128 threads/CTA (4 warps x 16 q-rows = 64 q). cp.async double-buffered.
// Buffer (16KB): K 0, V 8192. 2 buffers = 32KB. Swizzle c ^ (row&7).
// ---------------------------------------------------------------------------
#define ATTN_BUF 16384
#define ATTN_SMEM (2 * ATTN_BUF)

__global__ __launch_bounds__(128, 3) void attn_mma_kernel()
{
    const uint32_t sb = smem_u32(dynsm);

    const int tid  = threadIdx.x;
    const int lane = tid & 31;
    const int wid  = tid >> 5;          // 0..3
    const int bh   = blockIdx.y;
    const int b    = bh / NH;
    const int h    = bh % NH;
    const int q0   = blockIdx.x * 64;

    const size_t base = (size_t)b * SEQ * HIDDEN + h * DH;

    // ---- stage Q (64 rows; hi at 0, lo at 8192 — occupies buffer area) ----
#pragma unroll
    for (int j = 0; j < 4; j++) {
        int idx = j * 128 + tid;
        int r = idx >> 3, c = idx & 7;
        uint32_t d = (uint32_t)(r * 8 + (c ^ (r & 7))) * 16;
        cp_async16(sb + d,        (const uint4*)(g_qhi + base + (size_t)(q0 + r) * HIDDEN) + c);
        cp_async16(sb + 8192 + d, (const uint4*)(g_qlo + base + (size_t)(q0 + r) * HIDDEN) + c);
    }
    CP_COMMIT();
    CP_WAIT(0);
    __syncthreads();

    // ---- Q fragments (held in registers for whole kernel) ----
    uint32_t qh[4][4], ql[4][4];
    {
        int qrow = wid * 16 + (lane & 15);
        int key  = qrow & 7;
#pragma unroll
        for (int ks = 0; ks < 4; ks++) {
            int c = ks * 2 + (lane >> 4);
            uint32_t off = (uint32_t)(qrow * 8 + (c ^ key)) * 16;
            ldsm_x4(qh[ks], sb + off);
            ldsm_x4(ql[ks], sb + 8192 + off);
        }
    }
    __syncthreads();

    float accO[8][4];
#pragma unroll
    for (int n = 0; n < 8; n++)
#pragma unroll
        for (int t = 0; t < 4; t++) accO[n][t] = 0.0f;
    float m0 = -CUDART_INF_F, m1 = -CUDART_INF_F, l0 = 0.0f, l1 = 0.0f;

    const int sr = tid >> 3;           // 0..15
    const int sc = tid & 7;
    uint32_t sd[4];
#pragma unroll
    for (int u = 0; u < 4; u++) {
        int row = sr + u * 16;
        sd[u] = (uint32_t)(row * 8 + (sc ^ (row & 7))) * 16;
    }

    auto stageKV = [&](int kt, int buf) {
        uint32_t d = sb + (uint32_t)buf * ATTN_BUF;
#pragma unroll
        for (int u = 0; u < 4; u++) {
            size_t roff = base + (size_t)(kt + sr + u * 16) * HIDDEN;
            cp_async16(d + sd[u],        (const uint4*)(g_k + roff) + sc);
            cp_async16(d + 8192 + sd[u], (const uint4*)(g_v + roff) + sc);
        }
    };

    stageKV(0, 0);
    CP_COMMIT();

    for (int it = 0; it < SEQ / 64; it++) {
        if (it + 1 < SEQ / 64) {
            stageKV((it + 1) * 64, (it + 1) & 1);
            CP_COMMIT();
            CP_WAIT(1);
        } else {
            CP_WAIT(0);
        }
        __syncthreads();

        const uint32_t bK = sb + (uint32_t)(it & 1) * ATTN_BUF;
        const uint32_t bV = bK + 8192;

        // ---- S = Q.K^T (2-term: qh.K + ql.K) ----
        float s[8][4];
#pragma unroll
        for (int n = 0; n < 8; n++)
#pragma unroll
            for (int t = 0; t < 4; t++) s[n][t] = 0.0f;

#pragma unroll
        for (int ks = 0; ks < 4; ks++) {
#pragma unroll
            for (int pp = 0; pp < 4; pp += 2) {
                uint32_t k4[2][4];
#pragma unroll
                for (int d2 = 0; d2 < 2; d2++) {
                    int p = pp + d2;
                    int krow = (2 * p + ((lane >> 4) & 1)) * 8 + (lane & 7);
                    int c = ks * 2 + ((lane >> 3) & 1);
                    uint32_t off = (uint32_t)(krow * 8 + (c ^ (lane & 7))) * 16;
                    ldsm_x4(k4[d2], bK + off);
                }
                mma_f16(s[2 * pp + 0], qh[ks], &k4[0][0]);
                mma_f16(s[2 * pp + 1], qh[ks], &k4[0][2]);
                mma_f16(s[2 * pp + 2], qh[ks], &k4[1][0]);
                mma_f16(s[2 * pp + 3], qh[ks], &k4[1][2]);
                mma_f16(s[2 * pp + 0], ql[ks], &k4[0][0]);
                mma_f16(s[2 * pp + 1], ql[ks], &k4[0][2]);
                mma_f16(s[2 * pp + 2], ql[ks], &k4[1][0]);
                mma_f16(s[2 * pp + 3], ql[ks], &k4[1][2]);
            }
        }

        // ---- online softmax (rows r = lane>>2 and r+8) ----
        float rmax0 = -CUDART_INF_F, rmax1 = -CUDART_INF_F;
#pragma unroll
        for (int n = 0; n < 8; n++) {
            rmax0 = fmaxf(rmax0, fmaxf(s[n][0], s[n][1]));
            rmax1 = fmaxf(rmax1, fmaxf(s[n][2], s[n][3]));
        }
        rmax0 = fmaxf(rmax0, __shfl_xor_sync(0xffffffffu, rmax0, 1));
        rmax0 = fmaxf(rmax0, __shfl_xor_sync(0xffffffffu, rmax0, 2));
        rmax1 = fmaxf(rmax1, __shfl_xor_sync(0xffffffffu, rmax1, 1));
        rmax1 = fmaxf(rmax1, __shfl_xor_sync(0xffffffffu, rmax1, 2));
        float mn0 = fmaxf(m0, rmax0), mn1 = fmaxf(m1, rmax1);
        float a0 = __expf(m0 - mn0), a1 = __expf(m1 - mn1);
        float sum0 = 0.0f, sum1 = 0.0f;
#pragma unroll
        for (int n = 0; n < 8; n++) {
            s[n][0] = __expf(s[n][0] - mn0);
            s[n][1] = __expf(s[n][1] - mn0);
            s[n][2] = __expf(s[n][2] - mn1);
            s[n][3] = __expf(s[n][3] - mn1);
            sum0 += s[n][0] + s[n][1];
            sum1 += s[n][2] + s[n][3];
        }
        sum0 += __shfl_xor_sync(0xffffffffu, sum0, 1);
        sum0 += __shfl_xor_sync(0xffffffffu, sum0, 2);
        sum1 += __shfl_xor_sync(0xffffffffu, sum1, 1);
        sum1 += __shfl_xor_sync(0xffffffffu, sum1, 2);
        l0 = l0 * a0 + sum0;
        l1 = l1 * a1 + sum1;
        m0 = mn0; m1 = mn1;
#pragma unroll
        for (int n = 0; n < 8; n++) {
            accO[n][0] *= a0; accO[n][1] *= a0;
            accO[n][2] *= a1; accO[n][3] *= a1;
        }

        // ---- O += P.V (2-term: Ph.V + Pl.V); V via ldmatrix.x4.trans ----
#pragma unroll
        for (int j = 0; j < 4; j++) {
            uint32_t ph[4], pl[4];
            hsplit2(s[2 * j][0],     s[2 * j][1],     ph[0], pl[0]);
            hsplit2(s[2 * j][2],     s[2 * j][3],     ph[1], pl[1]);
            hsplit2(s[2 * j + 1][0], s[2 * j + 1][1], ph[2], pl[2]);
            hsplit2(s[2 * j + 1][2], s[2 * j + 1][3], ph[3], pl[3]);
            int vrow = j * 16 + (lane & 15);
#pragma unroll
            for (int qq = 0; qq < 4; qq += 2) {
                uint32_t v4[2][4];
#pragma unroll
                for (int d2 = 0; d2 < 2; d2++) {
                    int c = 2 * (qq + d2) + ((lane >> 4) & 1);
                    uint32_t off = (uint32_t)(vrow * 8 + (c ^ (vrow & 7))) * 16;
                    ldsm_x4_t(v4[d2], bV + off);
                }
                mma_f16(accO[2 * qq + 0], ph, &v4[0][0]);
                mma_f16(accO[2 * qq + 1], ph, &v4[0][2]);
                mma_f16(accO[2 * qq + 2], ph, &v4[1][0]);
                mma_f16(accO[2 * qq + 3], ph, &v4[1][2]);
                mma_f16(accO[2 * qq + 0], pl, &v4[0][0]);
                mma_f16(accO[2 * qq + 1], pl, &v4[0][2]);
                mma_f16(accO[2 * qq + 2], pl, &v4[1][0]);
                mma_f16(accO[2 * qq + 3], pl, &v4[1][2]);
            }
        }
        __syncthreads();
    }

    // ---- epilogue: normalize, write ctx hi/lo fp16 ----
    float inv0 = 1.0f / l0, inv1 = 1.0f / l1;
    int row = q0 + wid * 16 + (lane >> 2);
#pragma unroll
    for (int n2 = 0; n2 < 8; n2++) {
        int col = n2 * 8 + ((lane & 3) << 1);
        uint32_t h0, lo0, h1, lo1;
        hsplit2(accO[n2][0] * inv0, accO[n2][1] * inv0, h0, lo0);
        hsplit2(accO[n2][2] * inv1, accO[n2][3] * inv1, h1, lo1);
        size_t p0 = base + (size_t)row * HIDDEN + col;
        size_t p1 = base + (size_t)(row + 8) * HIDDEN + col;
        *(uint32_t*)(g_chi + p0) = h0;
        *(uint32_t*)(g_clo + p0) = lo0;
        *(uint32_t*)(g_chi + p1) = h1;
        *(uint32_t*)(g_clo + p1) = lo1;
    }
}

// ---------------------------------------------------------------------------
extern "C" void kernel_launch(void* const* d_in, const int* in_sizes, int n_in,
                              void* d_out, int out_size)
{
    const float* x  = (const float*)d_in[0];
    const float* wq = (const float*)d_in[1];
    const float* wk = (const float*)d_in[2];
    const float* wv = (const float*)d_in[3];
    const float* wo = (const float*)d_in[4];
    float* out = (float*)d_out;

    cudaFuncSetAttribute(qkv_mma_kernel, cudaFuncAttributeMaxDynamicSharedMemorySize,
                         GEMM_SMEM);
    cudaFuncSetAttribute(proj_mma_kernel, cudaFuncAttributeMaxDynamicSharedMemorySize,
                         GEMM_SMEM);
    cudaFuncSetAttribute(attn_mma_kernel, cudaFuncAttributeMaxDynamicSharedMemorySize,
                         ATTN_SMEM);

    const int nx4 = (int)(NELEM / 4);
    const int nw4 = (int)(WELEM / 4);

    split_x_kernel<<<(nx4 + 255) / 256, 256>>>(x);
    dim3 gcw((nw4 + 255) / 256, 4);
    conv_w_kernel<<<gcw, 256>>>(wq, wk, wv, wo);

    dim3 gqkv(HIDDEN / 128, MTOT / 128, 3);    // (6, 64, 3)
    qkv_mma_kernel<<<gqkv, 256, GEMM_SMEM>>>();

    dim3 gattn(SEQ / 64, BATCH * NH);          // (32, 48)
    attn_mma_kernel<<<gattn, 128, ATTN_SMEM>>>();

    dim3 gproj(HIDDEN / 128, MTOT / 128);      // (6, 64)
    proj_mma_kernel<<<gproj, 256, GEMM_SMEM>>>(out);
}